// round 3
// baseline (speedup 1.0000x reference)
#include <cuda_runtime.h>

// Problem constants (match reference_code)
constexpr int D  = 128;
constexpr int NE = 500000;
constexpr int NG = 200000;
constexpr int NM = 40000;

// Tile config
constexpr int BM  = 64;      // rows per block
constexpr int BN  = 128;     // output cols (= D)
constexpr int KC  = 32;      // K chunk staged in smem
constexpr int SXT = BM + 4;  // padded stride of transposed tiles

// Scatter-add scratch (no cudaMalloc allowed)
__device__ float g_agg[(size_t)NM * D];

__global__ void clear_agg_kernel() {
    int i = blockIdx.x * blockDim.x + threadIdx.x;
    if (i < NM * D) g_agg[i] = 0.0f;
}

// Inner-product micro-kernel on one staged KC chunk.
// AsT: [KC][SXT] transposed A chunk, Ws: [KC][BN] weight chunk.
__device__ __forceinline__ void fma_chunk(const float* __restrict__ AsT,
                                          const float* __restrict__ Ws,
                                          float acc[4][8], int r0, int j0) {
#pragma unroll 8
    for (int kk = 0; kk < KC; ++kk) {
        float4 a4  = *(const float4*)(AsT + kk * SXT + r0);
        float4 w0  = *(const float4*)(Ws + kk * BN + j0);
        float4 w1v = *(const float4*)(Ws + kk * BN + j0 + 4);
        float av[4] = {a4.x, a4.y, a4.z, a4.w};
        float wv[8] = {w0.x, w0.y, w0.z, w0.w, w1v.x, w1v.y, w1v.z, w1v.w};
#pragma unroll
        for (int i = 0; i < 4; ++i)
#pragma unroll
            for (int j = 0; j < 8; ++j)
                acc[i][j] += av[i] * wv[j];
    }
}

// Stage a KC-wide weight chunk W[c:c+KC][0:128] into Ws.
__device__ __forceinline__ void load_w_chunk(const float* __restrict__ W, int c,
                                             float* __restrict__ Ws, int tid) {
    for (int t = tid; t < KC * (BN / 4); t += 256) {
        int kk = t >> 5;
        int c4 = t & 31;
        ((float4*)Ws)[t] = ((const float4*)(W + (size_t)(c + kk) * BN))[c4];
    }
}

// MODE 0: edge (gather 3-way concat, LN, atomic scatter to g_agg)
// MODE 1: grid node MLP (K1=128, residual, store)
// MODE 2: mesh node MLP (K1=256 = [g_agg, mesh_feat], residual, store)
template <int K1, int MODE>
__global__ __launch_bounds__(256) void mlp_fused(
    const float* __restrict__ in0,        // edge: g2m_efeat; grid: grid_feat; mesh: mesh_feat
    const float* __restrict__ grid_feat,  // edge only
    const float* __restrict__ mesh_feat,  // edge only
    const int*   __restrict__ src_idx,    // edge only
    const int*   __restrict__ dst_idx,    // edge only
    const float* __restrict__ w1, const float* __restrict__ b1,
    const float* __restrict__ w2, const float* __restrict__ b2,
    const float* __restrict__ gam, const float* __restrict__ bet,
    float* __restrict__ out, int nrows)
{
    extern __shared__ float sm[];
    float* XsT  = sm;                    // [KC][SXT]  streamed X chunk (transposed)
    float* HsT  = XsT + KC * SXT;        // [128][SXT] hidden activations (transposed)
    float* Ws   = HsT + BN * SXT;        // [KC][128]  weight chunk
    int*   srcs = (int*)(Ws + KC * BN);  // [BM]
    int*   dsts = srcs + BM;             // [BM]

    const int tid  = threadIdx.x;
    const int tx   = tid & 15;   // column group (16)
    const int ty   = tid >> 4;   // row group (16)
    const int r0   = ty * 4;
    const int j0   = tx * 8;
    const int row0 = blockIdx.x * BM;

    if (MODE == 0) {
        if (tid < BM) {
            int e = row0 + tid;
            srcs[tid] = (e < nrows) ? src_idx[e] : 0;
            dsts[tid] = (e < nrows) ? dst_idx[e] : 0;
        }
    }

    float acc[4][8];
#pragma unroll
    for (int i = 0; i < 4; ++i)
#pragma unroll
        for (int j = 0; j < 8; ++j) acc[i][j] = 0.f;

    // ---- GEMM1: stream X and W1 in KC chunks ----
    for (int c = 0; c < K1; c += KC) {
        __syncthreads();   // prior chunk fully consumed (also covers srcs/dsts on c==0)
        // stage X chunk: columns [c, c+KC), transposed
        for (int t = tid; t < BM * (KC / 4); t += 256) {
            int r   = t >> 3;         // row in tile (KC/4 == 8)
            int c4l = t & 7;          // local float4 index
            int c4  = (c >> 2) + c4l; // global float4 column
            int row = row0 + r;
            float4 v = make_float4(0.f, 0.f, 0.f, 0.f);
            if (row < nrows) {
                if (MODE == 0) {
                    if (c4 < 32)      v = *(const float4*)(in0       + (size_t)row     * D + c4 * 4);
                    else if (c4 < 64) v = *(const float4*)(grid_feat + (size_t)srcs[r] * D + (c4 - 32) * 4);
                    else              v = *(const float4*)(mesh_feat + (size_t)dsts[r] * D + (c4 - 64) * 4);
                } else if (MODE == 2) {
                    if (c4 < 32)      v = *(const float4*)(g_agg + (size_t)row * D + c4 * 4);
                    else              v = *(const float4*)(in0   + (size_t)row * D + (c4 - 32) * 4);
                } else {
                    v = *(const float4*)(in0 + (size_t)row * D + c4 * 4);
                }
            }
            int k = c4l * 4;
            XsT[(k + 0) * SXT + r] = v.x;
            XsT[(k + 1) * SXT + r] = v.y;
            XsT[(k + 2) * SXT + r] = v.z;
            XsT[(k + 3) * SXT + r] = v.w;
        }
        load_w_chunk(w1, c, Ws, tid);
        __syncthreads();
        fma_chunk(XsT, Ws, acc, r0, j0);
    }

    // ---- bias + SiLU -> HsT (transposed) ----
    {
        float b1r[8];
#pragma unroll
        for (int j = 0; j < 8; ++j) b1r[j] = __ldg(b1 + j0 + j);
#pragma unroll
        for (int i = 0; i < 4; ++i)
#pragma unroll
            for (int j = 0; j < 8; ++j) {
                float h = acc[i][j] + b1r[j];
                h = h / (1.f + __expf(-h));
                HsT[(j0 + j) * SXT + (r0 + i)] = h;
            }
    }

#pragma unroll
    for (int i = 0; i < 4; ++i)
#pragma unroll
        for (int j = 0; j < 8; ++j) acc[i][j] = 0.f;

    // ---- GEMM2: [BM x 128] @ [128 x 128], A = HsT (resident) ----
    for (int c = 0; c < BN; c += KC) {
        __syncthreads();   // first iter: HsT writes visible + prior Ws consumed
        load_w_chunk(w2, c, Ws, tid);
        __syncthreads();
        fma_chunk(HsT + c * SXT, Ws, acc, r0, j0);
    }

    // ---- bias2 + LayerNorm ----
    float b2r[8], gr[8], br[8];
#pragma unroll
    for (int j = 0; j < 8; ++j) {
        b2r[j] = __ldg(b2 + j0 + j);
        gr[j]  = __ldg(gam + j0 + j);
        br[j]  = __ldg(bet + j0 + j);
    }
    float s[4], ss[4];
#pragma unroll
    for (int i = 0; i < 4; ++i) {
        s[i] = 0.f; ss[i] = 0.f;
#pragma unroll
        for (int j = 0; j < 8; ++j) {
            float v = acc[i][j] + b2r[j];
            acc[i][j] = v;
            s[i]  += v;
            ss[i] += v * v;
        }
    }
#pragma unroll
    for (int m = 1; m < 16; m <<= 1) {
#pragma unroll
        for (int i = 0; i < 4; ++i) {
            s[i]  += __shfl_xor_sync(0xffffffffu, s[i],  m);
            ss[i] += __shfl_xor_sync(0xffffffffu, ss[i], m);
        }
    }

#pragma unroll
    for (int i = 0; i < 4; ++i) {
        int row = row0 + r0 + i;
        float mu   = s[i] * (1.f / 128.f);
        float var  = ss[i] * (1.f / 128.f) - mu * mu;
        float rstd = rsqrtf(var + 1e-5f);
        if (MODE == 0) {
            if (row < nrows) {
                int dnode = dsts[r0 + i];
                float* dstp = g_agg + (size_t)dnode * D + j0;
#pragma unroll
                for (int j = 0; j < 8; ++j) {
                    float val = (acc[i][j] - mu) * rstd * gr[j] + br[j];
                    atomicAdd(dstp + j, val);
                }
            }
        } else {
            if (row < nrows) {
                const float* resp = in0 + (size_t)row * D + j0;  // residual source
                float o[8];
#pragma unroll
                for (int j = 0; j < 8; ++j)
                    o[j] = (acc[i][j] - mu) * rstd * gr[j] + br[j] + __ldg(resp + j);
                float4* op = (float4*)(out + (size_t)row * D + j0);
                op[0] = make_float4(o[0], o[1], o[2], o[3]);
                op[1] = make_float4(o[4], o[5], o[6], o[7]);
            }
        }
    }
}

static inline int smem_bytes() {
    return (KC * SXT + BN * SXT + KC * BN) * 4 + 2 * BM * 4;
}

extern "C" void kernel_launch(void* const* d_in, const int* in_sizes, int n_in,
                              void* d_out, int out_size) {
    const float* g2m       = (const float*)d_in[0];
    const float* grid_feat = (const float*)d_in[1];
    const float* mesh_feat = (const float*)d_in[2];
    const int*   src_idx   = (const int*)d_in[3];
    const int*   dst_idx   = (const int*)d_in[4];
    const float* ew1 = (const float*)d_in[5];
    const float* eb1 = (const float*)d_in[6];
    const float* ew2 = (const float*)d_in[7];
    const float* eb2 = (const float*)d_in[8];
    const float* eg  = (const float*)d_in[9];
    const float* ebt = (const float*)d_in[10];
    const float* sw1 = (const float*)d_in[11];
    const float* sb1 = (const float*)d_in[12];
    const float* sw2 = (const float*)d_in[13];
    const float* sb2 = (const float*)d_in[14];
    const float* sg  = (const float*)d_in[15];
    const float* sbt = (const float*)d_in[16];
    const float* dw1 = (const float*)d_in[17];
    const float* db1 = (const float*)d_in[18];
    const float* dw2 = (const float*)d_in[19];
    const float* db2 = (const float*)d_in[20];
    const float* dg  = (const float*)d_in[21];
    const float* dbt = (const float*)d_in[22];

    float* out_grid = (float*)d_out;
    float* out_mesh = out_grid + (size_t)NG * D;

    const int smB = smem_bytes();  // ~60.4 KB -> 3 CTAs/SM
    static int attr_done = 0;
    if (!attr_done) {
        cudaFuncSetAttribute(mlp_fused<384, 0>, cudaFuncAttributeMaxDynamicSharedMemorySize, smB);
        cudaFuncSetAttribute(mlp_fused<128, 1>, cudaFuncAttributeMaxDynamicSharedMemorySize, smB);
        cudaFuncSetAttribute(mlp_fused<256, 2>, cudaFuncAttributeMaxDynamicSharedMemorySize, smB);
        attr_done = 1;
    }

    clear_agg_kernel<<<(NM * D + 1023) / 1024, 1024>>>();

    mlp_fused<384, 0><<<(NE + BM - 1) / BM, 256, smB>>>(
        g2m, grid_feat, mesh_feat, src_idx, dst_idx,
        ew1, eb1, ew2, eb2, eg, ebt, nullptr, NE);

    mlp_fused<256, 2><<<(NM + BM - 1) / BM, 256, smB>>>(
        mesh_feat, nullptr, nullptr, nullptr, nullptr,
        dw1, db1, dw2, db2, dg, dbt, out_mesh, NM);

    mlp_fused<128, 1><<<(NG + BM - 1) / BM, 256, smB>>>(
        grid_feat, nullptr, nullptr, nullptr, nullptr,
        sw1, sb1, sw2, sb2, sg, sbt, out_grid, NG);
}

// round 5
// speedup vs baseline: 1.4886x; 1.4886x over previous
#include <cuda_runtime.h>
#include <cuda_bf16.h>
#include <cstdint>

// ---------------- problem constants ----------------
constexpr int D  = 128;
constexpr int NE = 500000;
constexpr int NG = 200000;
constexpr int NM = 40000;
constexpr int TM = 128;   // rows per CTA

// weight image offsets (elements) into g_w_hi / g_w_lo (plain [K][128] row-major)
constexpr int OFF_EW1 = 0;                    // K=384
constexpr int OFF_EW2 = OFF_EW1 + 384 * 128;
constexpr int OFF_SW1 = OFF_EW2 + 128 * 128;
constexpr int OFF_SW2 = OFF_SW1 + 128 * 128;
constexpr int OFF_DW1 = OFF_SW2 + 128 * 128;  // K=256
constexpr int OFF_DW2 = OFF_DW1 + 256 * 128;
constexpr int W_TOT   = OFF_DW2 + 128 * 128;  // 147456

__device__ __align__(16) __nv_bfloat16 g_w_hi[W_TOT];
__device__ __align__(16) __nv_bfloat16 g_w_lo[W_TOT];
__device__ __align__(16) float g_agg[(size_t)NM * D];

// ---------------- smem layout (bytes) ----------------
constexpr int SO_SRC = 0;          // srcs[128] int
constexpr int SO_DST = 512;        // dsts[128] int
constexpr int SO_PS  = 1024;       // psum[128][2] f32
constexpr int SO_PQ  = 2048;       // pssq[128][2] f32
constexpr int SA_STRIDE = 80;      // A chunk row: 32 bf16 = 64B + 16 pad
constexpr int SB_STRIDE = 272;     // B chunk row: 128 bf16 = 256B + 16 pad
constexpr int SH_STRIDE = 272;     // H row: 128 bf16 + pad
constexpr int SO_A   = 4096;                          // A_hi 128*80   = 10240
constexpr int SO_AL  = SO_A + 128 * SA_STRIDE;        // A_lo
constexpr int SO_B   = SO_AL + 128 * SA_STRIDE;       // B_hi 32*272   = 8704
constexpr int SO_BL  = SO_B + 32 * SB_STRIDE;         // B_lo
constexpr int SO_H   = SO_BL + 32 * SB_STRIDE;        // H_hi 128*272  = 34816
constexpr int SO_HL  = SO_H + 128 * SH_STRIDE;        // H_lo
constexpr int SMEMSZ = SO_HL + 128 * SH_STRIDE;       // 111616
constexpr int FB_STRIDE = 132;     // f32 LN buffer stride (floats), overlays H

// ---------------- PTX helpers ----------------
__device__ __forceinline__ uint32_t smem_u32(const void* p) {
    uint32_t a;
    asm("{ .reg .u64 t; cvta.to.shared.u64 t, %1; cvt.u32.u64 %0, t; }" : "=r"(a) : "l"(p));
    return a;
}
__device__ __forceinline__ void ldmA(uint32_t a[4], uint32_t addr) {
    asm volatile("ldmatrix.sync.aligned.m8n8.x4.shared.b16 {%0,%1,%2,%3}, [%4];"
                 : "=r"(a[0]), "=r"(a[1]), "=r"(a[2]), "=r"(a[3]) : "r"(addr));
}
__device__ __forceinline__ void ldmBT(uint32_t b[2], uint32_t addr) {
    asm volatile("ldmatrix.sync.aligned.m8n8.x2.trans.shared.b16 {%0,%1}, [%2];"
                 : "=r"(b[0]), "=r"(b[1]) : "r"(addr));
}
__device__ __forceinline__ void mma16816(float c[4], const uint32_t a[4], const uint32_t b[2]) {
    asm volatile("mma.sync.aligned.m16n8k16.row.col.f32.bf16.bf16.f32 "
                 "{%0,%1,%2,%3}, {%4,%5,%6,%7}, {%8,%9}, {%0,%1,%2,%3};"
                 : "+f"(c[0]), "+f"(c[1]), "+f"(c[2]), "+f"(c[3])
                 : "r"(a[0]), "r"(a[1]), "r"(a[2]), "r"(a[3]), "r"(b[0]), "r"(b[1]));
}
// pack two floats -> bf16x2 (lo -> low half / lower address)
__device__ __forceinline__ uint32_t pack_bf16(float lo, float hi) {
    uint32_t r;
    asm("cvt.rn.bf16x2.f32 %0, %1, %2;" : "=r"(r) : "f"(hi), "f"(lo));
    return r;
}
__device__ __forceinline__ void split2(float v, float& hf, float& lf) {
    __nv_bfloat16 h = __float2bfloat16(v);
    hf = __bfloat162float(h);
    lf = v - hf;
}
__device__ __forceinline__ void red_add4(float* p, float a, float b, float c, float d) {
    asm volatile("red.global.add.v4.f32 [%0], {%1,%2,%3,%4};"
                 :: "l"(p), "f"(a), "f"(b), "f"(c), "f"(d) : "memory");
}

// ---------------- prep kernels ----------------
__global__ void prep_weights(const float* __restrict__ ew1, const float* __restrict__ ew2,
                             const float* __restrict__ sw1, const float* __restrict__ sw2,
                             const float* __restrict__ dw1, const float* __restrict__ dw2) {
    int i = blockIdx.x * blockDim.x + threadIdx.x;
    if (i >= W_TOT) return;
    const float* src; int base;
    if      (i < OFF_EW2) { src = ew1; base = OFF_EW1; }
    else if (i < OFF_SW1) { src = ew2; base = OFF_EW2; }
    else if (i < OFF_SW2) { src = sw1; base = OFF_SW1; }
    else if (i < OFF_DW1) { src = sw2; base = OFF_SW2; }
    else if (i < OFF_DW2) { src = dw1; base = OFF_DW1; }
    else                  { src = dw2; base = OFF_DW2; }
    float v = src[i - base];
    float hf, lf; split2(v, hf, lf);
    g_w_hi[i] = __float2bfloat16(hf);
    g_w_lo[i] = __float2bfloat16(lf);
}
__global__ void clear_agg_kernel() {
    int i = blockIdx.x * blockDim.x + threadIdx.x;
    if (i < NM * D / 4) ((float4*)g_agg)[i] = make_float4(0.f, 0.f, 0.f, 0.f);
}

// ---------------- gather helper ----------------
template <int MODE>
__device__ __forceinline__ float4 loadA(const float* __restrict__ in0,
                                        const float* __restrict__ gf,
                                        const float* __restrict__ mf,
                                        const int* srcs, const int* dsts,
                                        int row, int r, int c4) {
    if (MODE == 0) {
        if (c4 < 32) return *(const float4*)(in0 + (size_t)row * D + c4 * 4);
        if (c4 < 64) return *(const float4*)(gf + (size_t)srcs[r] * D + (c4 - 32) * 4);
        return *(const float4*)(mf + (size_t)dsts[r] * D + (c4 - 64) * 4);
    } else if (MODE == 2) {
        if (c4 < 32) return *(const float4*)(g_agg + (size_t)row * D + c4 * 4);
        return *(const float4*)(in0 + (size_t)row * D + (c4 - 32) * 4);
    }
    return *(const float4*)(in0 + (size_t)row * D + c4 * 4);
}

// stage one 32-K chunk of a weight image into B_hi/B_lo smem (padded rows)
__device__ __forceinline__ void stage_B(char* smem, int woff, int ch, int tid) {
    const __nv_bfloat16* wh = g_w_hi + woff + ch * 32 * 128;
    const __nv_bfloat16* wl = g_w_lo + woff + ch * 32 * 128;
    for (int t = tid; t < 512; t += 256) {
        int r = t >> 4, q = t & 15;
        *(uint4*)(smem + SO_B  + r * SB_STRIDE + q * 16) = *(const uint4*)(wh + r * 128 + q * 8);
        *(uint4*)(smem + SO_BL + r * SB_STRIDE + q * 16) = *(const uint4*)(wl + r * 128 + q * 8);
    }
}

// run one 32-K chunk of split-bf16 MMAs; A at (abase_hi, abase_hi+adelta), rows stride astride
__device__ __forceinline__ void mma_chunk(uint32_t sb, uint32_t abase, uint32_t adelta,
                                          int astride, int kbyte0, float acc[2][8][4],
                                          int wr, int wc, int lane) {
#pragma unroll
    for (int k16 = 0; k16 < 2; ++k16) {
        uint32_t ah[2][4], al[2][4];
#pragma unroll
        for (int i = 0; i < 2; ++i) {
            uint32_t ad = abase + (wr * 32 + i * 16 + (lane & 15)) * astride
                        + kbyte0 + k16 * 32 + (lane >> 4) * 16;
            ldmA(ah[i], ad);
            ldmA(al[i], ad + adelta);
        }
#pragma unroll
        for (int j = 0; j < 8; ++j) {
            uint32_t bh[2], bl[2];
            uint32_t bd = sb + SO_B + (k16 * 16 + (lane & 15)) * SB_STRIDE
                        + (wc * 64 + j * 8) * 2;
            ldmBT(bh, bd);
            ldmBT(bl, bd + (SO_BL - SO_B));
            mma16816(acc[0][j], ah[0], bh);
            mma16816(acc[1][j], ah[1], bh);
            mma16816(acc[0][j], ah[0], bl);
            mma16816(acc[1][j], ah[1], bl);
            mma16816(acc[0][j], al[0], bh);
            mma16816(acc[1][j], al[1], bh);
        }
    }
}

// MODE 0: edge (gather concat, LN, red.v4 scatter)  MODE 1: grid  MODE 2: mesh
template <int K1, int MODE>
__global__ __launch_bounds__(256, 1) void mlp_hmma(
    const float* __restrict__ in0, const float* __restrict__ gf, const float* __restrict__ mf,
    const int* __restrict__ src_idx, const int* __restrict__ dst_idx,
    int w1off, int w2off,
    const float* __restrict__ b1, const float* __restrict__ b2,
    const float* __restrict__ gam, const float* __restrict__ bet,
    float* __restrict__ out, int nrows)
{
    extern __shared__ char smem[];
    const uint32_t sb = smem_u32(smem);
    const int tid = threadIdx.x, wid = tid >> 5, lane = tid & 31;
    const int wr = wid & 3, wc = wid >> 2;      // 4x2 warp grid: 32 rows x 64 cols
    const int gid = lane >> 2, tq = lane & 3;
    const int row0 = blockIdx.x * TM;
    constexpr int NC1 = K1 / 32;

    int* srcs = (int*)(smem + SO_SRC);
    int* dsts = (int*)(smem + SO_DST);
    if (MODE == 0) {
        for (int i = tid; i < 128; i += 256) {
            int e = row0 + i;
            srcs[i] = (e < nrows) ? src_idx[e] : 0;
            dsts[i] = (e < nrows) ? dst_idx[e] : 0;
        }
    }

    float acc[2][8][4];
#pragma unroll
    for (int i = 0; i < 2; ++i)
#pragma unroll
        for (int j = 0; j < 8; ++j)
#pragma unroll
            for (int q = 0; q < 4; ++q) acc[i][j][q] = 0.f;

    // ================= GEMM1 =================
    for (int ch = 0; ch < NC1; ++ch) {
        __syncthreads();
        // stage A chunk (gather + split + pack)
        for (int t = tid; t < 1024; t += 256) {
            int r = t >> 3, q = t & 7;
            int row = row0 + r;
            float4 v = make_float4(0.f, 0.f, 0.f, 0.f);
            if (row < nrows) v = loadA<MODE>(in0, gf, mf, srcs, dsts, row, r, ch * 8 + q);
            float h0, l0, h1, l1, h2, l2, h3, l3;
            split2(v.x, h0, l0); split2(v.y, h1, l1);
            split2(v.z, h2, l2); split2(v.w, h3, l3);
            *(uint2*)(smem + SO_A  + r * SA_STRIDE + q * 8) =
                make_uint2(pack_bf16(h0, h1), pack_bf16(h2, h3));
            *(uint2*)(smem + SO_AL + r * SA_STRIDE + q * 8) =
                make_uint2(pack_bf16(l0, l1), pack_bf16(l2, l3));
        }
        stage_B(smem, w1off, ch, tid);
        __syncthreads();
        mma_chunk(sb, sb + SO_A, SO_AL - SO_A, SA_STRIDE, 0, acc, wr, wc, lane);
    }

    // ===== epilogue1: bias + SiLU -> H (bf16 hi/lo in smem) =====
#pragma unroll
    for (int i = 0; i < 2; ++i) {
        int ra = wr * 32 + i * 16 + gid;   // row A
#pragma unroll
        for (int j = 0; j < 8; ++j) {
            int col = wc * 64 + j * 8 + tq * 2;
            float bb0 = __ldg(b1 + col), bb1 = __ldg(b1 + col + 1);
            float y0 = acc[i][j][0] + bb0, y1 = acc[i][j][1] + bb1;
            float y2 = acc[i][j][2] + bb0, y3 = acc[i][j][3] + bb1;
            y0 = y0 / (1.f + __expf(-y0)); y1 = y1 / (1.f + __expf(-y1));
            y2 = y2 / (1.f + __expf(-y2)); y3 = y3 / (1.f + __expf(-y3));
            float h0, l0, h1, l1, h2, l2, h3, l3;
            split2(y0, h0, l0); split2(y1, h1, l1);
            split2(y2, h2, l2); split2(y3, h3, l3);
            *(uint32_t*)(smem + SO_H  + ra * SH_STRIDE + col * 2)        = pack_bf16(h0, h1);
            *(uint32_t*)(smem + SO_HL + ra * SH_STRIDE + col * 2)        = pack_bf16(l0, l1);
            *(uint32_t*)(smem + SO_H  + (ra + 8) * SH_STRIDE + col * 2)  = pack_bf16(h2, h3);
            *(uint32_t*)(smem + SO_HL + (ra + 8) * SH_STRIDE + col * 2)  = pack_bf16(l2, l3);
        }
    }
#pragma unroll
    for (int i = 0; i < 2; ++i)
#pragma unroll
        for (int j = 0; j < 8; ++j)
#pragma unroll
            for (int q = 0; q < 4; ++q) acc[i][j][q] = 0.f;

    // ================= GEMM2: H[128x128] @ W2 =================
    for (int ch = 0; ch < 4; ++ch) {
        __syncthreads();   // H visible (ch0) / B buf free
        stage_B(smem, w2off, ch, tid);
        __syncthreads();
        mma_chunk(sb, sb + SO_H, SO_HL - SO_H, SH_STRIDE, ch * 64, acc, wr, wc, lane);
    }

    // ===== epilogue2: bias + LayerNorm + output =====
    __syncthreads();   // all H reads done -> overlay f32 buffer
    float* fbuf = (float*)(smem + SO_H);
#pragma unroll
    for (int i = 0; i < 2; ++i) {
        int ra = wr * 32 + i * 16 + gid;
#pragma unroll
        for (int j = 0; j < 8; ++j) {
            int col = wc * 64 + j * 8 + tq * 2;
            float bb0 = __ldg(b2 + col), bb1 = __ldg(b2 + col + 1);
            fbuf[ra * FB_STRIDE + col]           = acc[i][j][0] + bb0;
            fbuf[ra * FB_STRIDE + col + 1]       = acc[i][j][1] + bb1;
            fbuf[(ra + 8) * FB_STRIDE + col]     = acc[i][j][2] + bb0;
            fbuf[(ra + 8) * FB_STRIDE + col + 1] = acc[i][j][3] + bb1;
        }
    }
    __syncthreads();
    {
        const int row = tid >> 1, half = tid & 1;
        float v[64];
        float s = 0.f, ssq = 0.f;
        const float* rp = fbuf + row * FB_STRIDE + half * 64;
#pragma unroll
        for (int j = 0; j < 64; ++j) { float y = rp[j]; v[j] = y; s += y; ssq += y * y; }
        float* psum = (float*)(smem + SO_PS);
        float* pssq = (float*)(smem + SO_PQ);
        psum[row * 2 + half] = s;
        pssq[row * 2 + half] = ssq;
        __syncthreads();
        float st  = psum[row * 2] + psum[row * 2 + 1];
        float sst = pssq[row * 2] + pssq[row * 2 + 1];
        float mu   = st * (1.f / 128.f);
        float var  = sst * (1.f / 128.f) - mu * mu;
        float rstd = rsqrtf(var + 1e-5f);
        int grow = row0 + row;
        if (grow < nrows) {
            const int cb = half * 64;
#pragma unroll
            for (int j = 0; j < 64; ++j)
                v[j] = (v[j] - mu) * rstd * __ldg(gam + cb + j) + __ldg(bet + cb + j);
            if (MODE == 0) {
                float* bp = g_agg + (size_t)dsts[row] * D + cb;
#pragma unroll
                for (int j = 0; j < 64; j += 4)
                    red_add4(bp + j, v[j], v[j + 1], v[j + 2], v[j + 3]);
            } else {
                const float4* rsp = (const float4*)(in0 + (size_t)grow * D + cb);
                float4*       op  = (float4*)(out + (size_t)grow * D + cb);
#pragma unroll
                for (int q = 0; q < 16; ++q) {
                    float4 r4 = rsp[q];
                    op[q] = make_float4(v[4 * q] + r4.x, v[4 * q + 1] + r4.y,
                                        v[4 * q + 2] + r4.z, v[4 * q + 3] + r4.w);
                }
            }
        }
    }
}

// ---------------- launch ----------------
extern "C" void kernel_launch(void* const* d_in, const int* in_sizes, int n_in,
                              void* d_out, int out_size) {
    const float* g2m   = (const float*)d_in[0];
    const float* gfeat = (const float*)d_in[1];
    const float* mfeat = (const float*)d_in[2];
    const int*   src   = (const int*)d_in[3];
    const int*   dst   = (const int*)d_in[4];
    const float* ew1 = (const float*)d_in[5],  *eb1 = (const float*)d_in[6];
    const float* ew2 = (const float*)d_in[7],  *eb2 = (const float*)d_in[8];
    const float* eg  = (const float*)d_in[9],  *ebt = (const float*)d_in[10];
    const float* sw1 = (const float*)d_in[11], *sb1 = (const float*)d_in[12];
    const float* sw2 = (const float*)d_in[13], *sb2 = (const float*)d_in[14];
    const float* sg  = (const float*)d_in[15], *sbt = (const float*)d_in[16];
    const float* dw1 = (const float*)d_in[17], *db1 = (const float*)d_in[18];
    const float* dw2 = (const float*)d_in[19], *db2 = (const float*)d_in[20];
    const float* dg  = (const float*)d_in[21], *dbt = (const float*)d_in[22];

    float* out_grid = (float*)d_out;
    float* out_mesh = out_grid + (size_t)NG * D;

    static int attr_done = 0;
    if (!attr_done) {
        cudaFuncSetAttribute(mlp_hmma<384, 0>, cudaFuncAttributeMaxDynamicSharedMemorySize, SMEMSZ);
        cudaFuncSetAttribute(mlp_hmma<256, 2>, cudaFuncAttributeMaxDynamicSharedMemorySize, SMEMSZ);
        cudaFuncSetAttribute(mlp_hmma<128, 1>, cudaFuncAttributeMaxDynamicSharedMemorySize, SMEMSZ);
        attr_done = 1;
    }

    prep_weights<<<(W_TOT + 255) / 256, 256>>>(ew1, ew2, sw1, sw2, dw1, dw2);
    clear_agg_kernel<<<(NM * D / 4 + 255) / 256, 256>>>();

    mlp_hmma<384, 0><<<(NE + TM - 1) / TM, 256, SMEMSZ>>>(
        g2m, gfeat, mfeat, src, dst, OFF_EW1, OFF_EW2,
        eb1, eb2, eg, ebt, nullptr, NE);

    mlp_hmma<256, 2><<<(NM + TM - 1) / TM, 256, SMEMSZ>>>(
        mfeat, nullptr, nullptr, nullptr, nullptr, OFF_DW1, OFF_DW2,
        db1, db2, dg, dbt, out_mesh, NM);

    mlp_hmma<128, 1><<<(NG + TM - 1) / TM, 256, SMEMSZ>>>(
        gfeat, nullptr, nullptr, nullptr, nullptr, OFF_SW1, OFF_SW2,
        sb1, sb2, sg, sbt, out_grid, NG);
}

// round 6
// speedup vs baseline: 2.4422x; 1.6406x over previous
#include <cuda_runtime.h>
#include <cuda_bf16.h>
#include <cstdint>

// ---------------- problem constants ----------------
constexpr int D  = 128;
constexpr int NE = 500000;
constexpr int NG = 200000;
constexpr int NM = 40000;
constexpr int TM = 128;   // rows per CTA

// weight image offsets (elements) into g_w_hi / g_w_lo (plain [K][128] row-major)
constexpr int OFF_EW1 = 0;                    // K=384
constexpr int OFF_EW2 = OFF_EW1 + 384 * 128;
constexpr int OFF_SW1 = OFF_EW2 + 128 * 128;
constexpr int OFF_SW2 = OFF_SW1 + 128 * 128;
constexpr int OFF_DW1 = OFF_SW2 + 128 * 128;  // K=256
constexpr int OFF_DW2 = OFF_DW1 + 256 * 128;
constexpr int W_TOT   = OFF_DW2 + 128 * 128;  // 147456

__device__ __align__(16) __nv_bfloat16 g_w_hi[W_TOT];
__device__ __align__(16) __nv_bfloat16 g_w_lo[W_TOT];
__device__ __align__(16) float g_agg[(size_t)NM * D];

// ---------------- smem layout (bytes) ----------------
constexpr int SO_SRC = 0;          // srcs[128] int
constexpr int SO_DST = 512;        // dsts[128] int
constexpr int SO_PS  = 1024;       // psum[128][2] f32
constexpr int SO_PQ  = 2048;       // pssq[128][2] f32
constexpr int SA_STRIDE = 80;      // A chunk row: 32 bf16 = 64B + 16 pad
constexpr int SB_STRIDE = 272;     // B chunk row: 128 bf16 = 256B + 16 pad
constexpr int SH_STRIDE = 272;     // H row: 128 bf16 + pad
constexpr int SO_A   = 4096;                          // A_hi 128*80
constexpr int SO_AL  = SO_A + 128 * SA_STRIDE;        // A_lo
constexpr int SO_B   = SO_AL + 128 * SA_STRIDE;       // B_hi 32*272
constexpr int SO_BL  = SO_B + 32 * SB_STRIDE;         // B_lo
constexpr int SO_H   = SO_BL + 32 * SB_STRIDE;        // H_hi 128*272
constexpr int SO_HL  = SO_H + 128 * SH_STRIDE;        // H_lo
constexpr int SMEMSZ = SO_HL + 128 * SH_STRIDE;       // 111616 -> 2 CTAs/SM (223232 <= 228KB)
constexpr int FB_STRIDE = 132;     // f32 LN buffer stride (floats), overlays H

// ---------------- PTX helpers ----------------
__device__ __forceinline__ uint32_t smem_u32(const void* p) {
    uint32_t a;
    asm("{ .reg .u64 t; cvta.to.shared.u64 t, %1; cvt.u32.u64 %0, t; }" : "=r"(a) : "l"(p));
    return a;
}
__device__ __forceinline__ void ldmA(uint32_t a[4], uint32_t addr) {
    asm volatile("ldmatrix.sync.aligned.m8n8.x4.shared.b16 {%0,%1,%2,%3}, [%4];"
                 : "=r"(a[0]), "=r"(a[1]), "=r"(a[2]), "=r"(a[3]) : "r"(addr));
}
__device__ __forceinline__ void ldmBT(uint32_t b[2], uint32_t addr) {
    asm volatile("ldmatrix.sync.aligned.m8n8.x2.trans.shared.b16 {%0,%1}, [%2];"
                 : "=r"(b[0]), "=r"(b[1]) : "r"(addr));
}
__device__ __forceinline__ void mma16816(float c[4], const uint32_t a[4], const uint32_t b[2]) {
    asm volatile("mma.sync.aligned.m16n8k16.row.col.f32.bf16.bf16.f32 "
                 "{%0,%1,%2,%3}, {%4,%5,%6,%7}, {%8,%9}, {%0,%1,%2,%3};"
                 : "+f"(c[0]), "+f"(c[1]), "+f"(c[2]), "+f"(c[3])
                 : "r"(a[0]), "r"(a[1]), "r"(a[2]), "r"(a[3]), "r"(b[0]), "r"(b[1]));
}
// pack two floats -> bf16x2 (lo -> low half / lower address)
__device__ __forceinline__ uint32_t pack_bf16(float lo, float hi) {
    uint32_t r;
    asm("cvt.rn.bf16x2.f32 %0, %1, %2;" : "=r"(r) : "f"(hi), "f"(lo));
    return r;
}
__device__ __forceinline__ void split2(float v, float& hf, float& lf) {
    __nv_bfloat16 h = __float2bfloat16(v);
    hf = __bfloat162float(h);
    lf = v - hf;
}
__device__ __forceinline__ void red_add4(float* p, float a, float b, float c, float d) {
    asm volatile("red.global.add.v4.f32 [%0], {%1,%2,%3,%4};"
                 :: "l"(p), "f"(a), "f"(b), "f"(c), "f"(d) : "memory");
}
__device__ __forceinline__ void cp16(uint32_t dst, const void* src) {
    asm volatile("cp.async.cg.shared.global [%0], [%1], 16;" :: "r"(dst), "l"(src));
}
#define CP_COMMIT() asm volatile("cp.async.commit_group;" ::: "memory")
#define CP_WAIT0()  asm volatile("cp.async.wait_group 0;" ::: "memory")

// ---------------- prep kernels ----------------
__global__ void prep_weights(const float* __restrict__ ew1, const float* __restrict__ ew2,
                             const float* __restrict__ sw1, const float* __restrict__ sw2,
                             const float* __restrict__ dw1, const float* __restrict__ dw2) {
    int i = blockIdx.x * blockDim.x + threadIdx.x;
    if (i >= W_TOT) return;
    const float* src; int base;
    if      (i < OFF_EW2) { src = ew1; base = OFF_EW1; }
    else if (i < OFF_SW1) { src = ew2; base = OFF_EW2; }
    else if (i < OFF_SW2) { src = sw1; base = OFF_SW1; }
    else if (i < OFF_DW1) { src = sw2; base = OFF_SW2; }
    else if (i < OFF_DW2) { src = dw1; base = OFF_DW1; }
    else                  { src = dw2; base = OFF_DW2; }
    float v = src[i - base];
    float hf, lf; split2(v, hf, lf);
    g_w_hi[i] = __float2bfloat16(hf);
    g_w_lo[i] = __float2bfloat16(lf);
}
__global__ void clear_agg_kernel() {
    int i = blockIdx.x * blockDim.x + threadIdx.x;
    if (i < NM * D / 4) ((float4*)g_agg)[i] = make_float4(0.f, 0.f, 0.f, 0.f);
}

// ---------------- gather helper ----------------
template <int MODE>
__device__ __forceinline__ float4 loadA(const float* __restrict__ in0,
                                        const float* __restrict__ gf,
                                        const float* __restrict__ mf,
                                        const int* srcs, const int* dsts,
                                        int row, int r, int c4) {
    if (MODE == 0) {
        if (c4 < 32) return *(const float4*)(in0 + (size_t)row * D + c4 * 4);
        if (c4 < 64) return *(const float4*)(gf + (size_t)srcs[r] * D + (c4 - 32) * 4);
        return *(const float4*)(mf + (size_t)dsts[r] * D + (c4 - 64) * 4);
    } else if (MODE == 2) {
        if (c4 < 32) return *(const float4*)(g_agg + (size_t)row * D + c4 * 4);
        return *(const float4*)(in0 + (size_t)row * D + (c4 - 32) * 4);
    }
    return *(const float4*)(in0 + (size_t)row * D + c4 * 4);
}

// stage one 32-K chunk of a weight image into B_hi/B_lo smem via cp.async
__device__ __forceinline__ void stage_B(uint32_t sb, int woff, int ch, int tid) {
    const __nv_bfloat16* wh = g_w_hi + woff + ch * 32 * 128;
    const __nv_bfloat16* wl = g_w_lo + woff + ch * 32 * 128;
    for (int t = tid; t < 512; t += 256) {
        int r = t >> 4, q = t & 15;
        cp16(sb + SO_B  + r * SB_STRIDE + q * 16, wh + r * 128 + q * 8);
        cp16(sb + SO_BL + r * SB_STRIDE + q * 16, wl + r * 128 + q * 8);
    }
    CP_COMMIT();
}

// run one 32-K chunk of split-bf16 MMAs
__device__ __forceinline__ void mma_chunk(uint32_t sb, uint32_t abase, uint32_t adelta,
                                          int astride, int kbyte0, float acc[2][8][4],
                                          int wr, int wc, int lane) {
#pragma unroll
    for (int k16 = 0; k16 < 2; ++k16) {
        uint32_t ah[2][4], al[2][4];
#pragma unroll
        for (int i = 0; i < 2; ++i) {
            uint32_t ad = abase + (wr * 32 + i * 16 + (lane & 15)) * astride
                        + kbyte0 + k16 * 32 + (lane >> 4) * 16;
            ldmA(ah[i], ad);
            ldmA(al[i], ad + adelta);
        }
#pragma unroll
        for (int j = 0; j < 8; ++j) {
            uint32_t bh[2], bl[2];
            uint32_t bd = sb + SO_B + (k16 * 16 + (lane & 15)) * SB_STRIDE
                        + (wc * 64 + j * 8) * 2;
            ldmBT(bh, bd);
            ldmBT(bl, bd + (SO_BL - SO_B));
            mma16816(acc[0][j], ah[0], bh);
            mma16816(acc[1][j], ah[1], bh);
            mma16816(acc[0][j], ah[0], bl);
            mma16816(acc[1][j], ah[1], bl);
            mma16816(acc[0][j], al[0], bh);
            mma16816(acc[1][j], al[1], bh);
        }
    }
}

// MODE 0: edge (gather concat, LN, red.v4 scatter)  MODE 1: grid  MODE 2: mesh
template <int K1, int MODE>
__global__ __launch_bounds__(256, 2) void mlp_hmma(
    const float* __restrict__ in0, const float* __restrict__ gf, const float* __restrict__ mf,
    const int* __restrict__ src_idx, const int* __restrict__ dst_idx,
    int w1off, int w2off,
    const float* __restrict__ b1, const float* __restrict__ b2,
    const float* __restrict__ gam, const float* __restrict__ bet,
    float* __restrict__ out, int nrows)
{
    extern __shared__ char smem[];
    const uint32_t sb = smem_u32(smem);
    const int tid = threadIdx.x, wid = tid >> 5, lane = tid & 31;
    const int wr = wid & 3, wc = wid >> 2;      // 4x2 warp grid: 32 rows x 64 cols
    const int gid = lane >> 2, tq = lane & 3;
    const int row0 = blockIdx.x * TM;
    constexpr int NC1 = K1 / 32;

    int* srcs = (int*)(smem + SO_SRC);
    int* dsts = (int*)(smem + SO_DST);
    if (MODE == 0) {
        for (int i = tid; i < 128; i += 256) {
            int e = row0 + i;
            srcs[i] = (e < nrows) ? src_idx[e] : 0;
            dsts[i] = (e < nrows) ? dst_idx[e] : 0;
        }
    }

    float acc[2][8][4];
#pragma unroll
    for (int i = 0; i < 2; ++i)
#pragma unroll
        for (int j = 0; j < 8; ++j)
#pragma unroll
            for (int q = 0; q < 4; ++q) acc[i][j][q] = 0.f;

    // ================= GEMM1 =================
    for (int ch = 0; ch < NC1; ++ch) {
        __syncthreads();
        stage_B(sb, w1off, ch, tid);   // cp.async in flight during A conversion
        // stage A chunk (gather + split + pack)
        for (int t = tid; t < 1024; t += 256) {
            int r = t >> 3, q = t & 7;
            int row = row0 + r;
            float4 v = make_float4(0.f, 0.f, 0.f, 0.f);
            if (row < nrows) v = loadA<MODE>(in0, gf, mf, srcs, dsts, row, r, ch * 8 + q);
            float h0, l0, h1, l1, h2, l2, h3, l3;
            split2(v.x, h0, l0); split2(v.y, h1, l1);
            split2(v.z, h2, l2); split2(v.w, h3, l3);
            *(uint2*)(smem + SO_A  + r * SA_STRIDE + q * 8) =
                make_uint2(pack_bf16(h0, h1), pack_bf16(h2, h3));
            *(uint2*)(smem + SO_AL + r * SA_STRIDE + q * 8) =
                make_uint2(pack_bf16(l0, l1), pack_bf16(l2, l3));
        }
        CP_WAIT0();
        __syncthreads();
        mma_chunk(sb, sb + SO_A, SO_AL - SO_A, SA_STRIDE, 0, acc, wr, wc, lane);
    }

    // ===== epilogue1: bias + SiLU -> H (bf16 hi/lo in smem) =====
#pragma unroll
    for (int i = 0; i < 2; ++i) {
        int ra = wr * 32 + i * 16 + gid;
#pragma unroll
        for (int j = 0; j < 8; ++j) {
            int col = wc * 64 + j * 8 + tq * 2;
            float bb0 = __ldg(b1 + col), bb1 = __ldg(b1 + col + 1);
            float y0 = acc[i][j][0] + bb0, y1 = acc[i][j][1] + bb1;
            float y2 = acc[i][j][2] + bb0, y3 = acc[i][j][3] + bb1;
            y0 = y0 / (1.f + __expf(-y0)); y1 = y1 / (1.f + __expf(-y1));
            y2 = y2 / (1.f + __expf(-y2)); y3 = y3 / (1.f + __expf(-y3));
            float h0, l0, h1, l1, h2, l2, h3, l3;
            split2(y0, h0, l0); split2(y1, h1, l1);
            split2(y2, h2, l2); split2(y3, h3, l3);
            *(uint32_t*)(smem + SO_H  + ra * SH_STRIDE + col * 2)        = pack_bf16(h0, h1);
            *(uint32_t*)(smem + SO_HL + ra * SH_STRIDE + col * 2)        = pack_bf16(l0, l1);
            *(uint32_t*)(smem + SO_H  + (ra + 8) * SH_STRIDE + col * 2)  = pack_bf16(h2, h3);
            *(uint32_t*)(smem + SO_HL + (ra + 8) * SH_STRIDE + col * 2)  = pack_bf16(l2, l3);
        }
    }
#pragma unroll
    for (int i = 0; i < 2; ++i)
#pragma unroll
        for (int j = 0; j < 8; ++j)
#pragma unroll
            for (int q = 0; q < 4; ++q) acc[i][j][q] = 0.f;

    // ================= GEMM2: H[128x128] @ W2 =================
    for (int ch = 0; ch < 4; ++ch) {
        __syncthreads();   // H visible (ch0) / B buf free
        stage_B(sb, w2off, ch, tid);
        CP_WAIT0();
        __syncthreads();
        mma_chunk(sb, sb + SO_H, SO_HL - SO_H, SH_STRIDE, ch * 64, acc, wr, wc, lane);
    }

    // ===== epilogue2: bias + LayerNorm + output (two-pass streaming, low regs) =====
    __syncthreads();   // all H reads done -> overlay f32 buffer
    float* fbuf = (float*)(smem + SO_H);
#pragma unroll
    for (int i = 0; i < 2; ++i) {
        int ra = wr * 32 + i * 16 + gid;
#pragma unroll
        for (int j = 0; j < 8; ++j) {
            int col = wc * 64 + j * 8 + tq * 2;
            float bb0 = __ldg(b2 + col), bb1 = __ldg(b2 + col + 1);
            fbuf[ra * FB_STRIDE + col]           = acc[i][j][0] + bb0;
            fbuf[ra * FB_STRIDE + col + 1]       = acc[i][j][1] + bb1;
            fbuf[(ra + 8) * FB_STRIDE + col]     = acc[i][j][2] + bb0;
            fbuf[(ra + 8) * FB_STRIDE + col + 1] = acc[i][j][3] + bb1;
        }
    }
    __syncthreads();
    {
        const int row = tid >> 1, half = tid & 1;
        const int cb = half * 64;
        const float* rp = fbuf + row * FB_STRIDE + cb;
        // pass 1: sums (streaming, nothing retained)
        float s = 0.f, ssq = 0.f;
#pragma unroll
        for (int q = 0; q < 16; ++q) {
            float4 y4 = ((const float4*)rp)[q];
            s   += y4.x + y4.y + y4.z + y4.w;
            ssq += y4.x * y4.x + y4.y * y4.y + y4.z * y4.z + y4.w * y4.w;
        }
        float* psum = (float*)(smem + SO_PS);
        float* pssq = (float*)(smem + SO_PQ);
        psum[row * 2 + half] = s;
        pssq[row * 2 + half] = ssq;
        __syncthreads();
        float st  = psum[row * 2] + psum[row * 2 + 1];
        float sst = pssq[row * 2] + pssq[row * 2 + 1];
        float mu   = st * (1.f / 128.f);
        float var  = sst * (1.f / 128.f) - mu * mu;
        float rstd = rsqrtf(var + 1e-5f);
        int grow = row0 + row;
        if (grow < nrows) {
            // pass 2: normalize + output, one float4 at a time
            if (MODE == 0) {
                float* bp = g_agg + (size_t)dsts[row] * D + cb;
#pragma unroll
                for (int q = 0; q < 16; ++q) {
                    float4 y4 = ((const float4*)rp)[q];
                    int c = cb + q * 4;
                    float o0 = (y4.x - mu) * rstd * __ldg(gam + c)     + __ldg(bet + c);
                    float o1 = (y4.y - mu) * rstd * __ldg(gam + c + 1) + __ldg(bet + c + 1);
                    float o2 = (y4.z - mu) * rstd * __ldg(gam + c + 2) + __ldg(bet + c + 2);
                    float o3 = (y4.w - mu) * rstd * __ldg(gam + c + 3) + __ldg(bet + c + 3);
                    red_add4(bp + q * 4, o0, o1, o2, o3);
                }
            } else {
                const float4* rsp = (const float4*)(in0 + (size_t)grow * D + cb);
                float4*       op  = (float4*)(out + (size_t)grow * D + cb);
#pragma unroll
                for (int q = 0; q < 16; ++q) {
                    float4 y4 = ((const float4*)rp)[q];
                    float4 r4 = rsp[q];
                    int c = cb + q * 4;
                    op[q] = make_float4(
                        (y4.x - mu) * rstd * __ldg(gam + c)     + __ldg(bet + c)     + r4.x,
                        (y4.y - mu) * rstd * __ldg(gam + c + 1) + __ldg(bet + c + 1) + r4.y,
                        (y4.z - mu) * rstd * __ldg(gam + c + 2) + __ldg(bet + c + 2) + r4.z,
                        (y4.w - mu) * rstd * __ldg(gam + c + 3) + __ldg(bet + c + 3) + r4.w);
                }
            }
        }
    }
}

// ---------------- launch ----------------
extern "C" void kernel_launch(void* const* d_in, const int* in_sizes, int n_in,
                              void* d_out, int out_size) {
    const float* g2m   = (const float*)d_in[0];
    const float* gfeat = (const float*)d_in[1];
    const float* mfeat = (const float*)d_in[2];
    const int*   src   = (const int*)d_in[3];
    const int*   dst   = (const int*)d_in[4];
    const float* ew1 = (const float*)d_in[5],  *eb1 = (const float*)d_in[6];
    const float* ew2 = (const float*)d_in[7],  *eb2 = (const float*)d_in[8];
    const float* eg  = (const float*)d_in[9],  *ebt = (const float*)d_in[10];
    const float* sw1 = (const float*)d_in[11], *sb1 = (const float*)d_in[12];
    const float* sw2 = (const float*)d_in[13], *sb2 = (const float*)d_in[14];
    const float* sg  = (const float*)d_in[15], *sbt = (const float*)d_in[16];
    const float* dw1 = (const float*)d_in[17], *db1 = (const float*)d_in[18];
    const float* dw2 = (const float*)d_in[19], *db2 = (const float*)d_in[20];
    const float* dg  = (const float*)d_in[21], *dbt = (const float*)d_in[22];

    float* out_grid = (float*)d_out;
    float* out_mesh = out_grid + (size_t)NG * D;

    static int attr_done = 0;
    if (!attr_done) {
        cudaFuncSetAttribute(mlp_hmma<384, 0>, cudaFuncAttributeMaxDynamicSharedMemorySize, SMEMSZ);
        cudaFuncSetAttribute(mlp_hmma<256, 2>, cudaFuncAttributeMaxDynamicSharedMemorySize, SMEMSZ);
        cudaFuncSetAttribute(mlp_hmma<128, 1>, cudaFuncAttributeMaxDynamicSharedMemorySize, SMEMSZ);
        attr_done = 1;
    }

    prep_weights<<<(W_TOT + 255) / 256, 256>>>(ew1, ew2, sw1, sw2, dw1, dw2);
    clear_agg_kernel<<<(NM * D / 4 + 255) / 256, 256>>>();

    mlp_hmma<384, 0><<<(NE + TM - 1) / TM, 256, SMEMSZ>>>(
        g2m, gfeat, mfeat, src, dst, OFF_EW1, OFF_EW2,
        eb1, eb2, eg, ebt, nullptr, NE);

    mlp_hmma<256, 2><<<(NM + TM - 1) / TM, 256, SMEMSZ>>>(
        mfeat, nullptr, nullptr, nullptr, nullptr, OFF_DW1, OFF_DW2,
        db1, db2, dg, dbt, out_mesh, NM);

    mlp_hmma<128, 1><<<(NG + TM - 1) / TM, 256, SMEMSZ>>>(
        gfeat, nullptr, nullptr, nullptr, nullptr, OFF_SW1, OFF_SW2,
        sb1, sb2, sg, sbt, out_grid, NG);
}